// round 13
// baseline (speedup 1.0000x reference)
#include <cuda_runtime.h>
#include <cuda_fp16.h>
#include <cstdint>

#define Bsz 4
#define Hsz 16
#define Ssz 2048
#define Dsz 128
#define BM 128
#define BN 64
#define NT 128
#define NEG_INF -1e30f

// smem byte offsets; rows: Q/K 256B, Vt 128B
#define SM_Q 0
#define SM_K0 32768
#define SM_K1 49152
#define SM_V0 65536
#define SM_V1 81920
#define SM_TOTAL 98304   // 96 KB -> 2 CTAs/SM possible

// fp16 scratch (converted by prepass kernels each launch)
__device__ __half QhG[(size_t)Bsz * Hsz * Ssz * Dsz];  // [bh][m][d], pre-scaled
__device__ __half KhG[(size_t)Bsz * Hsz * Ssz * Dsz];  // [bh][n][d]
__device__ __half VtG[(size_t)Bsz * Hsz * Ssz * Dsz];  // [bh][d][n]  (transposed)

__device__ __forceinline__ uint32_t smem_u32(const void* p) {
  uint32_t a;
  asm("{ .reg .u64 t; cvta.to.shared.u64 t, %1; cvt.u32.u64 %0, t; }" : "=r"(a) : "l"(p));
  return a;
}
__device__ __forceinline__ void ldsm4(uint32_t* r, uint32_t addr) {
  asm volatile("ldmatrix.sync.aligned.m8n8.x4.shared.b16 {%0,%1,%2,%3}, [%4];"
               : "=r"(r[0]), "=r"(r[1]), "=r"(r[2]), "=r"(r[3])
               : "r"(addr));
}
#define CP16(dst, src) \
  asm volatile("cp.async.cg.shared.global [%0], [%1], 16;" ::"r"(dst), "l"(src) : "memory")
#define CP_COMMIT() asm volatile("cp.async.commit_group;" ::: "memory")
#define CP_WAIT1() asm volatile("cp.async.wait_group 1;" ::: "memory")
#define CP_WAIT0() asm volatile("cp.async.wait_group 0;" ::: "memory")

__device__ __forceinline__ void mma_f16(float* d, const uint32_t* a, const uint32_t* b) {
  asm volatile(
      "mma.sync.aligned.m16n8k16.row.col.f32.f16.f16.f32 "
      "{%0,%1,%2,%3}, {%4,%5,%6,%7}, {%8,%9}, {%0,%1,%2,%3};"
      : "+f"(d[0]), "+f"(d[1]), "+f"(d[2]), "+f"(d[3])
      : "r"(a[0]), "r"(a[1]), "r"(a[2]), "r"(a[3]), "r"(b[0]), "r"(b[1]));
}

// ---------------- prepass: fp32 -> fp16 (Q scaled; V transposed) ----------------
__global__ void prep_qk(const float* __restrict__ q, const float* __restrict__ k) {
  const float scl = 0.08838834764831845f;  // 1/sqrt(128)
  size_t i = ((size_t)blockIdx.x * blockDim.x + threadIdx.x) * 4;
  float4 qv = *(const float4*)(q + i);
  float4 kv = *(const float4*)(k + i);
  __half2* qo = (__half2*)(QhG + i);
  qo[0] = __floats2half2_rn(qv.x * scl, qv.y * scl);
  qo[1] = __floats2half2_rn(qv.z * scl, qv.w * scl);
  __half2* ko = (__half2*)(KhG + i);
  ko[0] = __floats2half2_rn(kv.x, kv.y);
  ko[1] = __floats2half2_rn(kv.z, kv.w);
}

__global__ void prep_v(const float* __restrict__ v) {
  __shared__ float tile[32][33];
  const int bh = blockIdx.z;
  const int n0 = blockIdx.x * 32, d0 = blockIdx.y * 32;
  const float* vp = v + (size_t)bh * Ssz * Dsz;
  const int tx = threadIdx.x, ty = threadIdx.y;
#pragma unroll
  for (int j = 0; j < 32; j += 8) tile[ty + j][tx] = vp[(size_t)(n0 + ty + j) * Dsz + d0 + tx];
  __syncthreads();
  __half* vt = VtG + (size_t)bh * Dsz * Ssz;
#pragma unroll
  for (int j = 0; j < 32; j += 8)
    vt[(size_t)(d0 + ty + j) * Ssz + n0 + tx] = __float2half_rn(tile[tx][ty + j]);
}

// ---------------- K/Vt tile prefetch via cp.async (swizzled dst) ----------------
__device__ __forceinline__ void kv_fetch(uint32_t smb, const __half* Kg, const __half* Vg,
                                         int n0, int buf, int tid) {
  const uint32_t kb = smb + (buf ? SM_K1 : SM_K0);
  const uint32_t vb = smb + (buf ? SM_V1 : SM_V0);
#pragma unroll 4
  for (int i = tid; i < 1024; i += NT) {  // K: 64 rows x 16 chunks (256B/row)
    int r = i >> 4, c = i & 15;
    CP16(kb + r * 256 + ((c * 16) ^ ((r & 7) * 16)),
         (const void*)(Kg + (size_t)(n0 + r) * Dsz + c * 8));
  }
#pragma unroll 4
  for (int i = tid; i < 1024; i += NT) {  // Vt: 128 rows x 8 chunks (128B/row)
    int r = i >> 3, c = i & 7;
    CP16(vb + r * 128 + ((c * 16) ^ ((r & 7) * 16)),
         (const void*)(Vg + (size_t)r * Ssz + n0 + c * 8));
  }
}

__global__ __launch_bounds__(NT, 2) void fa_fp16(float* __restrict__ gout) {
  extern __shared__ __align__(16) char sm[];
  const uint32_t smb = smem_u32(sm);

  const int bh = blockIdx.y;
  const int qt = gridDim.x - 1 - blockIdx.x;  // heavy q-tiles first
  const int m0 = qt * BM;
  const __half* Qg = QhG + (size_t)bh * Ssz * Dsz;
  const __half* Kg = KhG + (size_t)bh * Ssz * Dsz;
  const __half* Vg = VtG + (size_t)bh * Dsz * Ssz;
  float* out = gout + (size_t)bh * Ssz * Dsz;

  const int tid = threadIdx.x;
  const int warp = tid >> 5;
  const int lane = tid & 31;
  const int g = lane >> 2;
  const int t4 = lane & 3;

  // ldmatrix lane decomposition: tile index tl = lane>>3, row-in-tile rw = lane&7
  const uint32_t tl = (uint32_t)lane >> 3;
  const uint32_t rw = (uint32_t)lane & 7;
  const uint32_t tlo = tl & 1, thi = tl >> 1;

  // issue Q (128 rows x 16 chunks) + KV tile 0, one commit group
#pragma unroll 4
  for (int i = tid; i < 2048; i += NT) {
    int r = i >> 4, c = i & 15;
    CP16(smb + SM_Q + r * 256 + ((c * 16) ^ ((r & 7) * 16)),
         (const void*)(Qg + (size_t)(m0 + r) * Dsz + c * 8));
  }
  kv_fetch(smb, Kg, Vg, 0, 0, tid);
  CP_COMMIT();

  // precomputed ldmatrix row bases (row & 7 == rw for all patterns)
  // Q A-tiles: row = warp*32 + mt*16 + tlo*8 + rw ; chunk = kt*2 + thi
  uint32_t qbase[2];
#pragma unroll
  for (int mt = 0; mt < 2; mt++)
    qbase[mt] = smb + SM_Q + (uint32_t)(warp * 32 + mt * 16) * 256 + (tlo * 8 + rw) * 256;
  // K B-tiles: row = (ntpair*2 + thi)*8 + rw ; chunk = kt*2 + tlo
  const uint32_t krowoff = (thi * 8 + rw) * 256;
  // Vt B-tiles: row = (dtpair*2 + thi)*8 + rw ; chunk = kt*2 + tlo
  const uint32_t vrowoff = (thi * 8 + rw) * 128;

  float o[2][16][4];
  float mi[4] = {NEG_INF, NEG_INF, NEG_INF, NEG_INF};
  float li[4] = {0.f, 0.f, 0.f, 0.f};
#pragma unroll
  for (int a = 0; a < 2; a++)
#pragma unroll
    for (int b = 0; b < 16; b++)
#pragma unroll
      for (int c = 0; c < 4; c++) o[a][b][c] = 0.f;

  const int tmax = 2 * qt + 1;

  for (int t = 0; t <= tmax; t++) {
    const int n0 = t * BN;
    if (t < tmax) {  // prefetch next tile, then wait for current
      kv_fetch(smb, Kg, Vg, (t + 1) * BN, (t + 1) & 1, tid);
      CP_COMMIT();
      CP_WAIT1();
    } else {
      CP_WAIT0();
    }
    __syncthreads();

    const uint32_t kb = smb + ((t & 1) ? SM_K1 : SM_K0);
    const uint32_t vb = smb + ((t & 1) ? SM_V1 : SM_V0);

    // ---- S = Q @ K^T : 2 m-tiles x 8 n-tiles, k16 x 8 steps ----
    float sa[2][8][4];
#pragma unroll
    for (int a = 0; a < 2; a++)
#pragma unroll
      for (int b = 0; b < 8; b++)
#pragma unroll
        for (int c = 0; c < 4; c++) sa[a][b][c] = 0.f;

#pragma unroll
    for (int kt = 0; kt < 8; kt++) {
      uint32_t afr[2][4];
      {
        const uint32_t qch = ((uint32_t)(kt * 2) + thi) ^ rw;  // A: khalf = thi
        ldsm4(afr[0], qbase[0] + (qch << 4));
        ldsm4(afr[1], qbase[1] + (qch << 4));
      }
      const uint32_t kch = ((uint32_t)(kt * 2) + tlo) ^ rw;  // B: khalf = tlo
#pragma unroll
      for (int np = 0; np < 4; np++) {
        uint32_t bfr[4];  // = {b0(nt=2np), b1(2np), b0(2np+1), b1(2np+1)}
        ldsm4(bfr, kb + (uint32_t)(np * 16) * 256 + krowoff + (kch << 4));
        mma_f16(sa[0][2 * np + 0], afr[0], bfr + 0);
        mma_f16(sa[1][2 * np + 0], afr[1], bfr + 0);
        mma_f16(sa[0][2 * np + 1], afr[0], bfr + 2);
        mma_f16(sa[1][2 * np + 1], afr[1], bfr + 2);
      }
    }

    // ---- mask + online softmax; P packed to half2 IN REGISTERS ----
    uint32_t ph[2][8][2];
    const bool needmask = (n0 + BN - 1) > m0;
#pragma unroll
    for (int mt = 0; mt < 2; mt++) {
#pragma unroll
      for (int rr = 0; rr < 2; rr++) {
        const int st = mt * 2 + rr;
        const int grow = m0 + warp * 32 + mt * 16 + rr * 8 + g;
        if (needmask) {
#pragma unroll
          for (int nt = 0; nt < 8; nt++) {
            int col = n0 + nt * 8 + 2 * t4;
            if (col > grow) sa[mt][nt][rr * 2 + 0] = NEG_INF;
            if (col + 1 > grow) sa[mt][nt][rr * 2 + 1] = NEG_INF;
          }
        }
        float mx = NEG_INF;
#pragma unroll
        for (int nt = 0; nt < 8; nt++) {
          mx = fmaxf(mx, sa[mt][nt][rr * 2 + 0]);
          mx = fmaxf(mx, sa[mt][nt][rr * 2 + 1]);
        }
        mx = fmaxf(mx, __shfl_xor_sync(0xffffffffu, mx, 1));
        mx = fmaxf(mx, __shfl_xor_sync(0xffffffffu, mx, 2));

        const float mnew = fmaxf(mi[st], mx);
        const float alpha = __expf(mi[st] - mnew);
        float rs = 0.f;
#pragma unroll
        for (int nt = 0; nt < 8; nt++) {
          float p0 = __expf(sa[mt][nt][rr * 2 + 0] - mnew);
          float p1 = __expf(sa[mt][nt][rr * 2 + 1] - mnew);
          rs += p0 + p1;
          __half2 h = __floats2half2_rn(p0, p1);
          ph[mt][nt][rr] = *(uint32_t*)&h;
        }
        rs += __shfl_xor_sync(0xffffffffu, rs, 1);
        rs += __shfl_xor_sync(0xffffffffu, rs, 2);

        li[st] = li[st] * alpha + rs;
        mi[st] = mnew;
        if (alpha != 1.0f) {  // skip rescale when running max unchanged
#pragma unroll
          for (int dt = 0; dt < 16; dt++) {
            o[mt][dt][rr * 2 + 0] *= alpha;
            o[mt][dt][rr * 2 + 1] *= alpha;
          }
        }
      }
    }

    // ---- O += P @ Vt : k16 x 4 steps (n-tiles 2kt,2kt+1), 16 d-tiles ----
#pragma unroll
    for (int kt = 0; kt < 4; kt++) {
      uint32_t afr[2][4];
#pragma unroll
      for (int mt = 0; mt < 2; mt++) {
        afr[mt][0] = ph[mt][2 * kt + 0][0];
        afr[mt][1] = ph[mt][2 * kt + 0][1];
        afr[mt][2] = ph[mt][2 * kt + 1][0];
        afr[mt][3] = ph[mt][2 * kt + 1][1];
      }
      const uint32_t vch = ((uint32_t)(kt * 2) + tlo) ^ rw;
#pragma unroll
      for (int dp = 0; dp < 8; dp++) {
        uint32_t bfr[4];  // = {b0(dt=2dp), b1(2dp), b0(2dp+1), b1(2dp+1)}
        ldsm4(bfr, vb + (uint32_t)(dp * 16) * 128 + vrowoff + (vch << 4));
        mma_f16(o[0][2 * dp + 0], afr[0], bfr + 0);
        mma_f16(o[1][2 * dp + 0], afr[1], bfr + 0);
        mma_f16(o[0][2 * dp + 1], afr[0], bfr + 2);
        mma_f16(o[1][2 * dp + 1], afr[1], bfr + 2);
      }
    }
    __syncthreads();  // all warps done with this tile's K/Vt before overwrite
  }

  // ---- epilogue: normalize, store fp32 ----
#pragma unroll
  for (int mt = 0; mt < 2; mt++) {
#pragma unroll
    for (int rr = 0; rr < 2; rr++) {
      const float inv = 1.0f / li[mt * 2 + rr];
      const size_t rowaddr = (size_t)(m0 + warp * 32 + mt * 16 + rr * 8 + g) * Dsz;
#pragma unroll
      for (int dt = 0; dt < 16; dt++) {
        float2 ov;
        ov.x = o[mt][dt][rr * 2 + 0] * inv;
        ov.y = o[mt][dt][rr * 2 + 1] * inv;
        *(float2*)&out[rowaddr + dt * 8 + 2 * t4] = ov;
      }
    }
  }
}

extern "C" void kernel_launch(void* const* d_in, const int* in_sizes, int n_in,
                              void* d_out, int out_size) {
  const int qkv_elems = Bsz * Hsz * Ssz * Dsz;
  const float* ptrs[3] = {nullptr, nullptr, nullptr};
  int np = 0;
  for (int i = 0; i < n_in && np < 3; i++) {
    if (in_sizes[i] == qkv_elems) ptrs[np++] = (const float*)d_in[i];
  }

  // prepass: fp32 -> fp16 conversions (Q scaled, V transposed)
  prep_qk<<<qkv_elems / 4 / 256, 256>>>(ptrs[0], ptrs[1]);
  prep_v<<<dim3(Ssz / 32, Dsz / 32, Bsz * Hsz), dim3(32, 8)>>>(ptrs[2]);

  cudaFuncSetAttribute(fa_fp16, cudaFuncAttributeMaxDynamicSharedMemorySize, SM_TOTAL);
  dim3 grid(Ssz / BM, Bsz * Hsz);
  fa_fp16<<<grid, NT, SM_TOTAL>>>((float*)d_out);
}

// round 15
// speedup vs baseline: 1.4903x; 1.4903x over previous
#include <cuda_runtime.h>
#include <cuda_fp16.h>
#include <cstdint>

#define Bsz 4
#define Hsz 16
#define Ssz 2048
#define Dsz 128
#define BM 128
#define BN 64
#define NT 128
#define NEG_INF -1e30f

// smem byte offsets
#define SM_Q 0            // 32 KB packed A-fragments
#define SM_K0 32768       // 16 KB packed B-fragments (K)
#define SM_K1 49152
#define SM_V0 65536       // 16 KB packed B-fragments (Vt)
#define SM_V1 81920
#define SM_TOTAL 98304    // 96 KB -> 2 CTAs/SM

// packed fp16 scratch, fragment-ready layouts (written by prepass each launch)
// Qpk: [bh][mt 0..127][kt 0..7][lane 0..31] x 16B  (A-frag: rows g,g+8 x words c0,c0+4)
// Kpk: [bh][nt 0..255][kt 0..7][lane 0..31] x 8B   (B-frag: words c0,c0+4)
// Vpk: [bh][n64 0..31][kt 0..3][dt 0..15][lane] x 8B
__device__ uint4 QpkG[(size_t)Bsz * Hsz * 128 * 8 * 32];
__device__ uint2 KpkG[(size_t)Bsz * Hsz * 256 * 8 * 32];
__device__ uint2 VpkG[(size_t)Bsz * Hsz * 32 * 4 * 16 * 32];

__device__ __forceinline__ uint32_t smem_u32(const void* p) {
  uint32_t a;
  asm("{ .reg .u64 t; cvta.to.shared.u64 t, %1; cvt.u32.u64 %0, t; }" : "=r"(a) : "l"(p));
  return a;
}
__device__ __forceinline__ void lds128(uint32_t* r, uint32_t a) {
  asm volatile("ld.shared.v4.b32 {%0,%1,%2,%3}, [%4];"
               : "=r"(r[0]), "=r"(r[1]), "=r"(r[2]), "=r"(r[3]) : "r"(a));
}
__device__ __forceinline__ void lds64(uint32_t* r, uint32_t a) {
  asm volatile("ld.shared.v2.b32 {%0,%1}, [%2];" : "=r"(r[0]), "=r"(r[1]) : "r"(a));
}
__device__ __forceinline__ float ex2f(float x) {
  float y;
  asm("ex2.approx.f32 %0, %1;" : "=f"(y) : "f"(x));
  return y;
}
#define CP16(dst, src) \
  asm volatile("cp.async.cg.shared.global [%0], [%1], 16;" ::"r"(dst), "l"(src) : "memory")
#define CP_COMMIT() asm volatile("cp.async.commit_group;" ::: "memory")
#define CP_WAIT1() asm volatile("cp.async.wait_group 1;" ::: "memory")
#define CP_WAIT0() asm volatile("cp.async.wait_group 0;" ::: "memory")

__device__ __forceinline__ void mma_f16(float* d, const uint32_t* a, const uint32_t* b) {
  asm volatile(
      "mma.sync.aligned.m16n8k16.row.col.f32.f16.f16.f32 "
      "{%0,%1,%2,%3}, {%4,%5,%6,%7}, {%8,%9}, {%0,%1,%2,%3};"
      : "+f"(d[0]), "+f"(d[1]), "+f"(d[2]), "+f"(d[3])
      : "r"(a[0]), "r"(a[1]), "r"(a[2]), "r"(a[3]), "r"(b[0]), "r"(b[1]));
}

// ------------- prepass: Q -> A-fragment pack (scale includes log2e) -------------
__global__ void prep_qpk(const float* __restrict__ q) {
  const float scl = 0.08838834764831845f * 1.4426950408889634f;  // 1/sqrt(128) * log2e
  const uint32_t u = blockIdx.x * 256 + threadIdx.x;  // (bh, mt, kt, lane)
  const int lane = u & 31, kt = (u >> 5) & 7, mt = (u >> 8) & 127, bh = u >> 15;
  const int g = lane >> 2, t4 = lane & 3;
  const int r0 = mt * 16 + g;
  const int c0 = kt * 8 + t4;
  const float* q0 = q + ((size_t)bh * Ssz + r0) * Dsz;
  const float* q1 = q0 + 8 * Dsz;
  float2 f0 = *(const float2*)(q0 + 2 * c0);
  float2 f1 = *(const float2*)(q1 + 2 * c0);
  float2 f2 = *(const float2*)(q0 + 2 * c0 + 8);
  float2 f3 = *(const float2*)(q1 + 2 * c0 + 8);
  uint4 w;
  __half2 h;
  h = __floats2half2_rn(f0.x * scl, f0.y * scl); w.x = *(uint32_t*)&h;
  h = __floats2half2_rn(f1.x * scl, f1.y * scl); w.y = *(uint32_t*)&h;
  h = __floats2half2_rn(f2.x * scl, f2.y * scl); w.z = *(uint32_t*)&h;
  h = __floats2half2_rn(f3.x * scl, f3.y * scl); w.w = *(uint32_t*)&h;
  QpkG[u] = w;
}

// ------------- prepass: K -> B-fragment pack -------------
__global__ void prep_kpk(const float* __restrict__ k) {
  const uint32_t u = blockIdx.x * 256 + threadIdx.x;  // (bh, nt, kt, g)
  const int g = u & 7, kt = (u >> 3) & 7, nt = (u >> 6) & 255, bh = u >> 14;
  const int n = nt * 8 + g;
  const float* kp = k + ((size_t)bh * Ssz + n) * Dsz + kt * 16;
  float4 f[4];
#pragma unroll
  for (int i = 0; i < 4; i++) f[i] = *(const float4*)(kp + i * 4);
  const float* ff = (const float*)f;  // 16 floats = this (row, kt) chunk
  uint32_t w[8];
#pragma unroll
  for (int t4 = 0; t4 < 4; t4++)
#pragma unroll
    for (int wi = 0; wi < 2; wi++) {
      int d = (t4 + 4 * wi) * 2;
      __half2 h = __floats2half2_rn(ff[d], ff[d + 1]);
      w[t4 * 2 + wi] = h.x ? *(uint32_t*)&h : *(uint32_t*)&h;  // keep simple
    }
  uint4* dst = (uint4*)&KpkG[(size_t)u * 4];  // u indexes (bh,nt,kt,g) -> 4 uint2 = 32B
  dst[0] = make_uint4(w[0], w[1], w[2], w[3]);
  dst[1] = make_uint4(w[4], w[5], w[6], w[7]);
}

// ------------- prepass: V -> transposed B-fragment pack (smem staged) -------------
__global__ void prep_vpk(const float* __restrict__ v) {
  __shared__ float tile[64][33];
  const int n64 = blockIdx.x, dg = blockIdx.y, bh = blockIdx.z;
  const int n0 = n64 * 64, d0 = dg * 32;
  const int tx = threadIdx.x, ty = threadIdx.y;  // 32 x 8
  const float* vp = v + (size_t)bh * Ssz * Dsz;
#pragma unroll
  for (int j = 0; j < 8; j++)
    tile[ty + j * 8][tx] = vp[(size_t)(n0 + ty + j * 8) * Dsz + d0 + tx];
  __syncthreads();
  const uint32_t uu = ty * 32 + tx;
#pragma unroll
  for (int sblk = 0; sblk < 2; sblk++) {
    const uint32_t s = uu + sblk * 256;  // (kt, dtl, lane)
    const int lane = s & 31, dtl = (s >> 5) & 3, kt = s >> 7;
    const int g = lane >> 2, t4 = lane & 3;
    const int ln = 2 * (kt * 8 + t4);
    const int dl = dtl * 8 + g;
    __half2 h0 = __floats2half2_rn(tile[ln][dl], tile[ln + 1][dl]);
    __half2 h1 = __floats2half2_rn(tile[ln + 8][dl], tile[ln + 9][dl]);
    const int dt = dg * 4 + dtl;
    size_t idx = ((((size_t)bh * 32 + n64) * 4 + kt) * 16 + dt) * 32 + lane;
    VpkG[idx] = make_uint2(*(uint32_t*)&h0, *(uint32_t*)&h1);
  }
}

// ---------------- contiguous tile prefetch via cp.async ----------------
__device__ __forceinline__ void kv_fetch(uint32_t smb, const char* Ksrc, const char* Vsrc,
                                         int buf, int tid) {
  const uint32_t kb = smb + (buf ? SM_K1 : SM_K0);
  const uint32_t vb = smb + (buf ? SM_V1 : SM_V0);
#pragma unroll 8
  for (int i = tid; i < 1024; i += NT) CP16(kb + i * 16, Ksrc + i * 16);
#pragma unroll 8
  for (int i = tid; i < 1024; i += NT) CP16(vb + i * 16, Vsrc + i * 16);
}

__global__ __launch_bounds__(NT, 2) void fa_fp16(float* __restrict__ gout) {
  extern __shared__ __align__(16) char sm[];
  const uint32_t smb = smem_u32(sm);

  const int bh = blockIdx.y;
  const int qt = gridDim.x - 1 - blockIdx.x;  // heavy q-tiles first
  const int m0 = qt * BM;
  const char* Qsrc = (const char*)QpkG + (size_t)bh * 524288 + (size_t)qt * 32768;
  const char* Kbh = (const char*)KpkG + (size_t)bh * 524288;
  const char* Vbh = (const char*)VpkG + (size_t)bh * 524288;
  float* out = gout + (size_t)bh * Ssz * Dsz;

  const int tid = threadIdx.x;
  const int warp = tid >> 5;
  const int lane = tid & 31;
  const int g = lane >> 2;
  const int t4 = lane & 3;

  // Q (32 KB) + KV tile 0, one commit group
#pragma unroll 8
  for (int i = tid; i < 2048; i += NT) CP16(smb + SM_Q + i * 16, Qsrc + i * 16);
  kv_fetch(smb, Kbh, Vbh, 0, tid);
  CP_COMMIT();

  const uint32_t qbase = smb + SM_Q + (uint32_t)warp * 8192 + (uint32_t)lane * 16;
  const uint32_t loff = (uint32_t)lane * 8;

  float o[2][16][4];
  float mi[4] = {NEG_INF, NEG_INF, NEG_INF, NEG_INF};
  float li[4] = {0.f, 0.f, 0.f, 0.f};
#pragma unroll
  for (int a = 0; a < 2; a++)
#pragma unroll
    for (int b = 0; b < 16; b++)
#pragma unroll
      for (int c = 0; c < 4; c++) o[a][b][c] = 0.f;

  const int tmax = 2 * qt + 1;

  for (int t = 0; t <= tmax; t++) {
    const int n0 = t * BN;
    if (t < tmax) {
      kv_fetch(smb, Kbh + (size_t)(t + 1) * 16384, Vbh + (size_t)(t + 1) * 16384,
               (t + 1) & 1, tid);
      CP_COMMIT();
      CP_WAIT1();
    } else {
      CP_WAIT0();
    }
    __syncthreads();

    const uint32_t kb = smb + ((t & 1) ? SM_K1 : SM_K0) + loff;
    const uint32_t vb = smb + ((t & 1) ? SM_V1 : SM_V0) + loff;

    // ---- S = Q @ K^T ----
    float sa[2][8][4];
#pragma unroll
    for (int a = 0; a < 2; a++)
#pragma unroll
      for (int b = 0; b < 8; b++)
#pragma unroll
        for (int c = 0; c < 4; c++) sa[a][b][c] = 0.f;

#pragma unroll
    for (int kt = 0; kt < 8; kt++) {
      uint32_t afr[2][4];
      lds128(afr[0], qbase + (uint32_t)(0 * 8 + kt) * 512);
      lds128(afr[1], qbase + (uint32_t)(1 * 8 + kt) * 512);
#pragma unroll
      for (int nt = 0; nt < 8; nt++) {
        uint32_t bfr[2];
        lds64(bfr, kb + (uint32_t)(nt * 8 + kt) * 256);
        mma_f16(sa[0][nt], afr[0], bfr);
        mma_f16(sa[1][nt], afr[1], bfr);
      }
    }

    // ---- mask + online softmax (log2 domain); P packed in registers ----
    uint32_t ph[2][8][2];
    const bool needmask = (n0 + BN - 1) > m0;
#pragma unroll
    for (int mt = 0; mt < 2; mt++) {
#pragma unroll
      for (int rr = 0; rr < 2; rr++) {
        const int st = mt * 2 + rr;
        const int grow = m0 + warp * 32 + mt * 16 + rr * 8 + g;
        if (needmask) {
#pragma unroll
          for (int nt = 0; nt < 8; nt++) {
            int col = n0 + nt * 8 + 2 * t4;
            if (col > grow) sa[mt][nt][rr * 2 + 0] = NEG_INF;
            if (col + 1 > grow) sa[mt][nt][rr * 2 + 1] = NEG_INF;
          }
        }
        float mx = NEG_INF;
#pragma unroll
        for (int nt = 0; nt < 8; nt++) {
          mx = fmaxf(mx, sa[mt][nt][rr * 2 + 0]);
          mx = fmaxf(mx, sa[mt][nt][rr * 2 + 1]);
        }
        mx = fmaxf(mx, __shfl_xor_sync(0xffffffffu, mx, 1));
        mx = fmaxf(mx, __shfl_xor_sync(0xffffffffu, mx, 2));

        const float mnew = fmaxf(mi[st], mx);
        const float alpha = ex2f(mi[st] - mnew);
        float rs = 0.f;
#pragma unroll
        for (int nt = 0; nt < 8; nt++) {
          float p0 = ex2f(sa[mt][nt][rr * 2 + 0] - mnew);
          float p1 = ex2f(sa[mt][nt][rr * 2 + 1] - mnew);
          rs += p0 + p1;
          __half2 h = __floats2half2_rn(p0, p1);
          ph[mt][nt][rr] = *(uint32_t*)&h;
        }
        rs += __shfl_xor_sync(0xffffffffu, rs, 1);
        rs += __shfl_xor_sync(0xffffffffu, rs, 2);

        li[st] = li[st] * alpha + rs;
        mi[st] = mnew;
        if (alpha != 1.0f) {
#pragma unroll
          for (int dt = 0; dt < 16; dt++) {
            o[mt][dt][rr * 2 + 0] *= alpha;
            o[mt][dt][rr * 2 + 1] *= alpha;
          }
        }
      }
    }

    // ---- O += P @ Vt ----
#pragma unroll
    for (int kt = 0; kt < 4; kt++) {
      uint32_t afr[2][4];
#pragma unroll
      for (int mt = 0; mt < 2; mt++) {
        afr[mt][0] = ph[mt][2 * kt + 0][0];
        afr[mt][1] = ph[mt][2 * kt + 0][1];
        afr[mt][2] = ph[mt][2 * kt + 1][0];
        afr[mt][3] = ph[mt][2 * kt + 1][1];
      }
#pragma unroll
      for (int dt = 0; dt < 16; dt++) {
        uint32_t bfr[2];
        lds64(bfr, vb + (uint32_t)(kt * 16 + dt) * 256);
        mma_f16(o[0][dt], afr[0], bfr);
        mma_f16(o[1][dt], afr[1], bfr);
      }
    }
    __syncthreads();  // all warps done with this tile before buffer overwrite
  }

  // ---- epilogue: normalize, store fp32 ----
#pragma unroll
  for (int mt = 0; mt < 2; mt++) {
#pragma unroll
    for (int rr = 0; rr < 2; rr++) {
      const float inv = 1.0f / li[mt * 2 + rr];
      const size_t rowaddr = (size_t)(m0 + warp * 32 + mt * 16 + rr * 8 + g) * Dsz;
#pragma unroll
      for (int dt = 0; dt < 16; dt++) {
        float2 ov;
        ov.x = o[mt][dt][rr * 2 + 0] * inv;
        ov.y = o[mt][dt][rr * 2 + 1] * inv;
        *(float2*)&out[rowaddr + dt * 8 + 2 * t4] = ov;
      }
    }
  }
}

extern "C" void kernel_launch(void* const* d_in, const int* in_sizes, int n_in,
                              void* d_out, int out_size) {
  const int qkv_elems = Bsz * Hsz * Ssz * Dsz;
  const float* ptrs[3] = {nullptr, nullptr, nullptr};
  int np = 0;
  for (int i = 0; i < n_in && np < 3; i++) {
    if (in_sizes[i] == qkv_elems) ptrs[np++] = (const float*)d_in[i];
  }

  prep_qpk<<<Bsz * Hsz * 128 * 8 * 32 / 256, 256>>>(ptrs[0]);
  prep_kpk<<<Bsz * Hsz * 256 * 8 * 8 / 256, 256>>>(ptrs[1]);
  prep_vpk<<<dim3(32, 4, Bsz * Hsz), dim3(32, 8)>>>(ptrs[2]);

  cudaFuncSetAttribute(fa_fp16, cudaFuncAttributeMaxDynamicSharedMemorySize, SM_TOTAL);
  dim3 grid(Ssz / BM, Bsz * Hsz);
  fa_fp16<<<grid, NT, SM_TOTAL>>>((float*)d_out);
}